// round 8
// baseline (speedup 1.0000x reference)
#include <cuda_runtime.h>
#include <math.h>
#include <stdint.h>

// Problem constants
#define B 512
#define V 6890
#define J 24
#define NB 10
#define P 207           // (J-1)*9
#define N3 (V*3)        // 20670
#define KT 224          // padded GEMM K: 207 posedirs + 10 shapedirs + 7 zero
#define VS 20736        // padded column stride

__constant__ int c_parents[J] = {0,0,0,0,1,2,3,4,5,6,7,8,9,9,9,12,13,14,16,17,18,19,20,21};

// Scratch (device globals)
__device__ float g_jt[J*3];
__device__ float g_JS[J*3*NB];
__device__ float g_AT[KT*B];                // A^T (tf32-rounded): [k][b]
__device__ float g_rel[B*J*12];             // rel transforms, 3x4 row-major
__device__ float g_vposed[(size_t)B*VS];    // v_shaped + pose correction (padded)

__device__ __forceinline__ float tf32r(float x) {
    uint32_t y; asm("cvt.rna.tf32.f32 %0, %1;" : "=r"(y) : "f"(x));
    return __uint_as_float(y);
}

#define MMA_TF32(acc, a0,a1,a2,a3, b0,b1) \
    asm volatile( \
        "mma.sync.aligned.m16n8k8.row.col.f32.tf32.tf32.f32 " \
        "{%0,%1,%2,%3}, {%4,%5,%6,%7}, {%8,%9}, {%0,%1,%2,%3};\n" \
        : "+f"(acc[0]), "+f"(acc[1]), "+f"(acc[2]), "+f"(acc[3]) \
        : "r"(a0), "r"(a1), "r"(a2), "r"(a3), "r"(b0), "r"(b1))

// ---------------------------------------------------------------------------
// K1: jt / JS regression (tiny)
// ---------------------------------------------------------------------------
__global__ void k1_regress(const float* __restrict__ Jreg,
                           const float* __restrict__ vt,
                           const float* __restrict__ sd) {
    int j = blockIdx.x;
    int q = blockIdx.y;
    int tid = threadIdx.x;
    const float* jr = Jreg + (size_t)j * V;
    float acc = 0.f;
    if (q < 3) {
        for (int v = tid; v < V; v += 256) acc += jr[v] * vt[v*3 + q];
    } else {
        int kl = q - 3;
        for (int v = tid; v < V; v += 256) acc += jr[v] * sd[v*30 + kl];
    }
    __shared__ float red[256];
    red[tid] = acc;
    __syncthreads();
    for (int s = 128; s > 0; s >>= 1) {
        if (tid < s) red[tid] += red[tid + s];
        __syncthreads();
    }
    if (tid == 0) {
        if (q < 3) g_jt[j*3 + q] = red[0];
        else       g_JS[j*30 + (q-3)] = red[0];
    }
}

// ---------------------------------------------------------------------------
// K2: rodrigues + chain + rel transforms; fills tf32-rounded g_AT.
// ---------------------------------------------------------------------------
__global__ void k2_pose(const float* __restrict__ ro,
                        const float* __restrict__ pb,
                        const float* __restrict__ ph,
                        const float* __restrict__ betas,
                        const float* __restrict__ trans,
                        float* __restrict__ out_joints) {
    int b = blockIdx.x;
    int lane = threadIdx.x;

    __shared__ float rot[J][9];
    __shared__ float jnt[J][3];
    __shared__ float G[J][12];

    if (lane < J) {
        float r0, r1, r2;
        if (lane == 0)        { const float* p = ro + b*3;                 r0=p[0]; r1=p[1]; r2=p[2]; }
        else if (lane <= 21)  { const float* p = pb + b*63 + (lane-1)*3;   r0=p[0]; r1=p[1]; r2=p[2]; }
        else                  { const float* p = ph + b*6  + (lane-22)*3;  r0=p[0]; r1=p[1]; r2=p[2]; }

        float a2  = r0*r0 + r1*r1 + r2*r2 + 1e-8f;
        float ang = sqrtf(a2);
        float inv = 1.f / ang;
        float x = r0*inv, y = r1*inv, z = r2*inv;
        float c = cosf(ang), s = sinf(ang), o = 1.f - c;

        float R[9];
        R[0] = c + o*x*x;     R[1] = -s*z + o*x*y;  R[2] =  s*y + o*x*z;
        R[3] =  s*z + o*y*x;  R[4] = c + o*y*y;     R[5] = -s*x + o*y*z;
        R[6] = -s*y + o*z*x;  R[7] =  s*x + o*z*y;  R[8] = c + o*z*z;

        #pragma unroll
        for (int e = 0; e < 9; e++) rot[lane][e] = R[e];

        if (lane >= 1) {
            int base = (lane-1)*9;
            #pragma unroll
            for (int e = 0; e < 9; e++)
                g_AT[(base+e)*B + b] = tf32r(R[e] - ((e == 0 || e == 4 || e == 8) ? 1.f : 0.f));
        }

        float bt[NB];
        #pragma unroll
        for (int l = 0; l < NB; l++) bt[l] = betas[b*NB + l];
        #pragma unroll
        for (int k = 0; k < 3; k++) {
            float a = g_jt[lane*3 + k];
            #pragma unroll
            for (int l = 0; l < NB; l++) a += bt[l] * g_JS[lane*30 + k*10 + l];
            jnt[lane][k] = a;
        }
    }
    if (lane < NB)  g_AT[(P + lane)*B + b] = tf32r(betas[b*NB + lane]);
    if (lane >= 25) g_AT[(192 + lane)*B + b] = 0.f;   // rows 217..223
    __syncthreads();

    if (lane == 0) {
        #pragma unroll
        for (int m = 0; m < 3; m++) {
            G[0][m*4+0] = rot[0][m*3+0];
            G[0][m*4+1] = rot[0][m*3+1];
            G[0][m*4+2] = rot[0][m*3+2];
            G[0][m*4+3] = jnt[0][m];
        }
        for (int j = 1; j < J; j++) {
            int p = c_parents[j];
            float t0 = jnt[j][0] - jnt[p][0];
            float t1 = jnt[j][1] - jnt[p][1];
            float t2 = jnt[j][2] - jnt[p][2];
            #pragma unroll
            for (int m = 0; m < 3; m++) {
                float p0 = G[p][m*4+0], p1 = G[p][m*4+1], p2 = G[p][m*4+2], p3 = G[p][m*4+3];
                G[j][m*4+0] = p0*rot[j][0] + p1*rot[j][3] + p2*rot[j][6];
                G[j][m*4+1] = p0*rot[j][1] + p1*rot[j][4] + p2*rot[j][7];
                G[j][m*4+2] = p0*rot[j][2] + p1*rot[j][5] + p2*rot[j][8];
                G[j][m*4+3] = p0*t0 + p1*t1 + p2*t2 + p3;
            }
        }
    }
    __syncthreads();

    if (lane < J) {
        int j = lane;
        float tx = trans[b*3+0], ty = trans[b*3+1], tz = trans[b*3+2];
        float* oj = out_joints + ((size_t)b*J + j)*3;
        oj[0] = G[j][3]  + tx;
        oj[1] = G[j][7]  + ty;
        oj[2] = G[j][11] + tz;

        float* rl = g_rel + ((size_t)b*J + j)*12;
        #pragma unroll
        for (int m = 0; m < 3; m++) {
            float corr = G[j][m*4+0]*jnt[j][0] + G[j][m*4+1]*jnt[j][1] + G[j][m*4+2]*jnt[j][2];
            rl[m*4+0] = G[j][m*4+0];
            rl[m*4+1] = G[j][m*4+1];
            rl[m*4+2] = G[j][m*4+2];
            rl[m*4+3] = G[j][m*4+3] - corr;
        }
    }
}

// ---------------------------------------------------------------------------
// B-row loader for K3: raw fp32 bits (mma.tf32 hardware uses tf32 fields).
// ---------------------------------------------------------------------------
__device__ __forceinline__ void load_B_row(float* dst, int k, int cbase,
                                           const float* __restrict__ posedirs,
                                           const float* __restrict__ sd) {
    if (k < P) {
        if (cbase + 8 <= N3) {
            const float2* s = reinterpret_cast<const float2*>(posedirs + (size_t)k*N3 + cbase);
            #pragma unroll
            for (int i = 0; i < 4; i++) {
                float2 v = s[i];
                dst[2*i]   = v.x;
                dst[2*i+1] = v.y;
            }
        } else {
            #pragma unroll
            for (int i = 0; i < 8; i++) {
                int c = cbase + i;
                dst[i] = (c < N3) ? posedirs[(size_t)k*N3 + c] : 0.f;
            }
        }
    } else if (k < P + NB) {
        int l = k - P;
        #pragma unroll
        for (int i = 0; i < 8; i++) {
            int c = cbase + i;
            dst[i] = (c < N3) ? sd[(size_t)c*NB + l] : 0.f;
        }
    } else {
        #pragma unroll
        for (int i = 0; i < 8; i++) dst[i] = 0.f;
    }
}

// ---------------------------------------------------------------------------
// K3: TF32 GEMM, R5 single-sync double buffer, B loaded direct (no pack).
// ---------------------------------------------------------------------------
#define BK3 16
#define SST 136
__global__ void __launch_bounds__(256) k3_tf32(const float* __restrict__ vt,
                                               const float* __restrict__ posedirs,
                                               const float* __restrict__ sd) {
    __shared__ float sA[2][BK3][SST];
    __shared__ float sB[2][BK3][SST];

    int tid  = threadIdx.x;
    int warp = tid >> 5, lane = tid & 31;
    int wm = warp >> 2;
    int wn = warp & 3;
    int gr = lane >> 2;
    int tg = lane & 3;

    int c0 = blockIdx.x * 128;
    int b0 = blockIdx.y * 128;

    int lk = tid >> 4;
    int lc = (tid & 15) * 8;

    float acc[4][4][4];
    #pragma unroll
    for (int mi = 0; mi < 4; mi++)
        #pragma unroll
        for (int ni = 0; ni < 4; ni++)
            #pragma unroll
            for (int r = 0; r < 4; r++) acc[mi][ni][r] = 0.f;

    {
        const float4* ga = reinterpret_cast<const float4*>(g_AT + (size_t)lk*B + b0 + lc);
        float bv[8];
        load_B_row(bv, lk, c0 + lc, posedirs, sd);
        float4 a0 = ga[0], a1 = ga[1];
        *reinterpret_cast<float4*>(&sA[0][lk][lc])     = a0;
        *reinterpret_cast<float4*>(&sA[0][lk][lc + 4]) = a1;
        *reinterpret_cast<float4*>(&sB[0][lk][lc])     = *reinterpret_cast<float4*>(bv);
        *reinterpret_cast<float4*>(&sB[0][lk][lc + 4]) = *reinterpret_cast<float4*>(bv + 4);
    }
    __syncthreads();

    const int NST = KT / BK3;    // 14
    for (int st = 0; st < NST; st++) {
        float4 pa0, pa1;
        float pbv[8];
        bool has_next = (st + 1 < NST);
        if (has_next) {
            int k = (st + 1) * BK3 + lk;
            const float4* ga = reinterpret_cast<const float4*>(g_AT + (size_t)k*B + b0 + lc);
            pa0 = ga[0]; pa1 = ga[1];
            load_B_row(pbv, k, c0 + lc, posedirs, sd);
        }
        int buf = st & 1;

        #pragma unroll
        for (int ks = 0; ks < 2; ks++) {
            int kb = ks * 8;
            uint32_t bfr[4][2];
            #pragma unroll
            for (int ni = 0; ni < 4; ni++) {
                int n = wn*32 + ni*8 + gr;
                bfr[ni][0] = __float_as_uint(sB[buf][kb + tg][n]);
                bfr[ni][1] = __float_as_uint(sB[buf][kb + tg + 4][n]);
            }
            uint32_t afr[4][4];
            #pragma unroll
            for (int mi = 0; mi < 4; mi++) {
                int m = wm*64 + mi*16 + gr;
                afr[mi][0] = __float_as_uint(sA[buf][kb + tg][m]);
                afr[mi][1] = __float_as_uint(sA[buf][kb + tg][m + 8]);
                afr[mi][2] = __float_as_uint(sA[buf][kb + tg + 4][m]);
                afr[mi][3] = __float_as_uint(sA[buf][kb + tg + 4][m + 8]);
            }
            #pragma unroll
            for (int mi = 0; mi < 4; mi++)
                #pragma unroll
                for (int ni = 0; ni < 4; ni++)
                    MMA_TF32(acc[mi][ni], afr[mi][0], afr[mi][1], afr[mi][2], afr[mi][3],
                             bfr[ni][0], bfr[ni][1]);
        }

        if (has_next) {
            int nb = 1 - buf;
            *reinterpret_cast<float4*>(&sA[nb][lk][lc])     = pa0;
            *reinterpret_cast<float4*>(&sA[nb][lk][lc + 4]) = pa1;
            *reinterpret_cast<float4*>(&sB[nb][lk][lc])     = *reinterpret_cast<float4*>(pbv);
            *reinterpret_cast<float4*>(&sB[nb][lk][lc + 4]) = *reinterpret_cast<float4*>(pbv + 4);
            __syncthreads();
        }
    }

    #pragma unroll
    for (int mi = 0; mi < 4; mi++) {
        #pragma unroll
        for (int half = 0; half < 2; half++) {
            int b = b0 + wm*64 + mi*16 + gr + half*8;
            #pragma unroll
            for (int ni = 0; ni < 4; ni++) {
                int c = c0 + wn*32 + ni*8 + tg*2;
                float v0 = (c     < N3) ? vt[c]     : 0.f;
                float v1 = (c + 1 < N3) ? vt[c + 1] : 0.f;
                float2 o = make_float2(acc[mi][ni][half*2]     + v0,
                                       acc[mi][ni][half*2 + 1] + v1);
                *reinterpret_cast<float2*>(g_vposed + (size_t)b*VS + c) = o;
            }
        }
    }
}

// ---------------------------------------------------------------------------
// K4: tensor-core skinning. Per block: 64 verts x 8 batches.
// T[v, (bi,e)] = sum_j W[v,j] * rel_b[j,e]   (split-tf32, 3 mma terms)
// then out[m] = sum_n T[m*4+n]*vh[n] via in-register shfl reduction.
// ---------------------------------------------------------------------------
__global__ void __launch_bounds__(256) k4_skin_tc(const float* __restrict__ weights,
                                                  const float* __restrict__ trans,
                                                  float* __restrict__ out) {
    __shared__ float sWhi[J][72];    // [k=j][m=vert]
    __shared__ float sWlo[J][72];
    __shared__ float sRhi[J][136];   // [k=j][n = bi*16 + e]
    __shared__ float sRlo[J][136];

    int tid  = threadIdx.x;
    int warp = tid >> 5, lane = tid & 31;
    int wm = warp >> 2;      // 0..1: m-offset wm*32
    int wn = warp & 3;       // 0..3: n-offset wn*32 (2 batches)
    int gr = lane >> 2;      // 0..7
    int tg = lane & 3;       // 0..3

    int v0 = blockIdx.x * 64;
    int b0 = blockIdx.y * 8;

    // Load weights tile (64 x 24), split hi/lo
    for (int i = tid; i < 64*J; i += 256) {
        int m = i / J, j = i % J;
        int v = v0 + m;
        float w = (v < V) ? weights[(size_t)v*J + j] : 0.f;
        float hi = tf32r(w);
        sWhi[j][m] = hi;
        sWlo[j][m] = tf32r(w - hi);
    }
    // Load rel tiles (8 batches x 24 j x 16 cols, cols 12..15 = 0), split hi/lo
    for (int i = tid; i < 8*J*16; i += 256) {
        int bi = i / (J*16);
        int r  = i % (J*16);
        int j  = r / 16, e = r % 16;
        float val = (e < 12) ? g_rel[(((size_t)(b0+bi))*J + j)*12 + e] : 0.f;
        float hi = tf32r(val);
        sRhi[j][bi*16 + e] = hi;
        sRlo[j][bi*16 + e] = tf32r(val - hi);
    }
    __syncthreads();

    float acc[2][4][4];
    #pragma unroll
    for (int mi = 0; mi < 2; mi++)
        #pragma unroll
        for (int ni = 0; ni < 4; ni++)
            #pragma unroll
            for (int r = 0; r < 4; r++) acc[mi][ni][r] = 0.f;

    #pragma unroll
    for (int ksi = 0; ksi < 3; ksi++) {      // K = 24 = 3 x 8
        int kb = ksi * 8;
        uint32_t ahi[2][4], alo[2][4];
        #pragma unroll
        for (int mi = 0; mi < 2; mi++) {
            int m = wm*32 + mi*16 + gr;
            ahi[mi][0] = __float_as_uint(sWhi[kb + tg][m]);
            ahi[mi][1] = __float_as_uint(sWhi[kb + tg][m + 8]);
            ahi[mi][2] = __float_as_uint(sWhi[kb + tg + 4][m]);
            ahi[mi][3] = __float_as_uint(sWhi[kb + tg + 4][m + 8]);
            alo[mi][0] = __float_as_uint(sWlo[kb + tg][m]);
            alo[mi][1] = __float_as_uint(sWlo[kb + tg][m + 8]);
            alo[mi][2] = __float_as_uint(sWlo[kb + tg + 4][m]);
            alo[mi][3] = __float_as_uint(sWlo[kb + tg + 4][m + 8]);
        }
        #pragma unroll
        for (int ni = 0; ni < 4; ni++) {
            int n = wn*32 + ni*8 + gr;
            uint32_t bh0 = __float_as_uint(sRhi[kb + tg][n]);
            uint32_t bh1 = __float_as_uint(sRhi[kb + tg + 4][n]);
            uint32_t bl0 = __float_as_uint(sRlo[kb + tg][n]);
            uint32_t bl1 = __float_as_uint(sRlo[kb + tg + 4][n]);
            #pragma unroll
            for (int mi = 0; mi < 2; mi++) {
                MMA_TF32(acc[mi][ni], ahi[mi][0], ahi[mi][1], ahi[mi][2], ahi[mi][3], bh0, bh1);
                MMA_TF32(acc[mi][ni], alo[mi][0], alo[mi][1], alo[mi][2], alo[mi][3], bh0, bh1);
                MMA_TF32(acc[mi][ni], ahi[mi][0], ahi[mi][1], ahi[mi][2], ahi[mi][3], bl0, bl1);
            }
        }
    }

    // Epilogue. Thread holds T at rows (gr, gr+8) of m-frag, cols tg*2, tg*2+1
    // of each n-frag. n-frag ni -> batch (wn*2 + (ni>>1)), col half (ni&1).
    int tgl = tg & 1;          // selects (vx,vy) vs (vz,1)
    float selA = (float)(tg < 2);   // contributes to p[tg>>1==0 -> m0]
    #pragma unroll
    for (int bl = 0; bl < 2; bl++) {
        int bb = b0 + wn*2 + bl;
        float t0 = trans[bb*3+0], t1 = trans[bb*3+1], t2 = trans[bb*3+2];
        const float* vp = g_vposed + (size_t)bb * VS;
        #pragma unroll
        for (int mi = 0; mi < 2; mi++) {
            #pragma unroll
            for (int half = 0; half < 2; half++) {
                int v = v0 + wm*32 + mi*16 + gr + half*8;
                bool ok = (v < V);
                int vv = ok ? v : 0;
                float vx = vp[vv*3+0], vy = vp[vv*3+1], vz = vp[vv*3+2];
                float u0 = tgl ? vz : vx;
                float u1 = tgl ? 1.f : vy;

                // frag h=0 (ni = bl*2): cols e = tg*2, tg*2+1 -> row m = tg>>1
                float c0 = acc[mi][bl*2][half*2];
                float c1 = acc[mi][bl*2][half*2+1];
                float s01 = fmaf(c0, u0, c1*u1);
                float p0 = s01 * selA;           // tg<2 -> m0
                float p1 = s01 * (1.f - selA);   // tg>=2 -> m1
                // frag h=1 (ni = bl*2+1): cols e = 8+tg*2 -> m = 2 (tg<2), pad (tg>=2)
                float d0 = acc[mi][bl*2+1][half*2];
                float d1 = acc[mi][bl*2+1][half*2+1];
                float p2 = fmaf(d0, u0, d1*u1) * selA;

                // reduce over tg quad (lanes xor 1, xor 2)
                p0 += __shfl_xor_sync(0xffffffff, p0, 1);
                p1 += __shfl_xor_sync(0xffffffff, p1, 1);
                p2 += __shfl_xor_sync(0xffffffff, p2, 1);
                p0 += __shfl_xor_sync(0xffffffff, p0, 2);
                p1 += __shfl_xor_sync(0xffffffff, p1, 2);
                p2 += __shfl_xor_sync(0xffffffff, p2, 2);

                if (tg == 0 && ok) {
                    float* o = out + ((size_t)bb*V + v)*3;
                    o[0] = p0 + t0;
                    o[1] = p1 + t1;
                    o[2] = p2 + t2;
                }
            }
        }
    }
}

// ---------------------------------------------------------------------------
extern "C" void kernel_launch(void* const* d_in, const int* in_sizes, int n_in,
                              void* d_out, int out_size) {
    const float* root_orient = (const float*)d_in[0];
    const float* pose_body   = (const float*)d_in[1];
    const float* pose_hand   = (const float*)d_in[2];
    const float* betas       = (const float*)d_in[3];
    const float* trans       = (const float*)d_in[4];
    const float* v_template  = (const float*)d_in[5];
    const float* shapedirs   = (const float*)d_in[6];
    const float* posedirs    = (const float*)d_in[7];
    const float* J_regressor = (const float*)d_in[8];
    const float* weights     = (const float*)d_in[9];

    float* out = (float*)d_out;
    float* out_joints = out + (size_t)B * V * 3;

    k1_regress<<<dim3(J, 33), 256>>>(J_regressor, v_template, shapedirs);
    k2_pose<<<B, 32>>>(root_orient, pose_body, pose_hand, betas, trans, out_joints);
    k3_tf32<<<dim3(VS/128, B/128), 256>>>(v_template, posedirs, shapedirs);
    k4_skin_tc<<<dim3((V + 63)/64, B/8), 256>>>(weights, trans, out);
}

// round 11
// speedup vs baseline: 1.6642x; 1.6642x over previous
#include <cuda_runtime.h>
#include <math.h>
#include <stdint.h>

// Problem constants
#define B 512
#define V 6890
#define J 24
#define NB 10
#define P 207           // (J-1)*9
#define N3 (V*3)        // 20670
#define KT 224          // padded GEMM K: 207 posedirs + 10 shapedirs + 7 zero
#define VS 20736        // padded column stride

__constant__ int c_parents[J] = {0,0,0,0,1,2,3,4,5,6,7,8,9,9,9,12,13,14,16,17,18,19,20,21};

// Scratch (device globals)
__device__ float g_jt[J*3];
__device__ float g_JS[J*3*NB];
__device__ float g_AT[KT*B];                // A^T (tf32-rounded): [k][b]
__device__ float g_rel[B*J*12];             // rel transforms, 3x4 row-major
__device__ float g_vposed[(size_t)B*VS];    // v_shaped + pose correction (padded)

__device__ __forceinline__ float tf32r(float x) {
    uint32_t y; asm("cvt.rna.tf32.f32 %0, %1;" : "=r"(y) : "f"(x));
    return __uint_as_float(y);
}

#define MMA_TF32(acc, a0,a1,a2,a3, b0,b1) \
    asm volatile( \
        "mma.sync.aligned.m16n8k8.row.col.f32.tf32.tf32.f32 " \
        "{%0,%1,%2,%3}, {%4,%5,%6,%7}, {%8,%9}, {%0,%1,%2,%3};\n" \
        : "+f"(acc[0]), "+f"(acc[1]), "+f"(acc[2]), "+f"(acc[3]) \
        : "r"(a0), "r"(a1), "r"(a2), "r"(a3), "r"(b0), "r"(b1))

// ---------------------------------------------------------------------------
// K1: jt / JS regression (tiny)
// ---------------------------------------------------------------------------
__global__ void k1_regress(const float* __restrict__ Jreg,
                           const float* __restrict__ vt,
                           const float* __restrict__ sd) {
    int j = blockIdx.x;
    int q = blockIdx.y;
    int tid = threadIdx.x;
    const float* jr = Jreg + (size_t)j * V;
    float acc = 0.f;
    if (q < 3) {
        for (int v = tid; v < V; v += 256) acc += jr[v] * vt[v*3 + q];
    } else {
        int kl = q - 3;
        for (int v = tid; v < V; v += 256) acc += jr[v] * sd[v*30 + kl];
    }
    __shared__ float red[256];
    red[tid] = acc;
    __syncthreads();
    for (int s = 128; s > 0; s >>= 1) {
        if (tid < s) red[tid] += red[tid + s];
        __syncthreads();
    }
    if (tid == 0) {
        if (q < 3) g_jt[j*3 + q] = red[0];
        else       g_JS[j*30 + (q-3)] = red[0];
    }
}

// ---------------------------------------------------------------------------
// K2: rodrigues + chain + rel transforms; fills tf32-rounded g_AT.
// ---------------------------------------------------------------------------
__global__ void k2_pose(const float* __restrict__ ro,
                        const float* __restrict__ pb,
                        const float* __restrict__ ph,
                        const float* __restrict__ betas,
                        const float* __restrict__ trans,
                        float* __restrict__ out_joints) {
    int b = blockIdx.x;
    int lane = threadIdx.x;

    __shared__ float rot[J][9];
    __shared__ float jnt[J][3];
    __shared__ float G[J][12];

    if (lane < J) {
        float r0, r1, r2;
        if (lane == 0)        { const float* p = ro + b*3;                 r0=p[0]; r1=p[1]; r2=p[2]; }
        else if (lane <= 21)  { const float* p = pb + b*63 + (lane-1)*3;   r0=p[0]; r1=p[1]; r2=p[2]; }
        else                  { const float* p = ph + b*6  + (lane-22)*3;  r0=p[0]; r1=p[1]; r2=p[2]; }

        float a2  = r0*r0 + r1*r1 + r2*r2 + 1e-8f;
        float ang = sqrtf(a2);
        float inv = 1.f / ang;
        float x = r0*inv, y = r1*inv, z = r2*inv;
        float c = cosf(ang), s = sinf(ang), o = 1.f - c;

        float R[9];
        R[0] = c + o*x*x;     R[1] = -s*z + o*x*y;  R[2] =  s*y + o*x*z;
        R[3] =  s*z + o*y*x;  R[4] = c + o*y*y;     R[5] = -s*x + o*y*z;
        R[6] = -s*y + o*z*x;  R[7] =  s*x + o*z*y;  R[8] = c + o*z*z;

        #pragma unroll
        for (int e = 0; e < 9; e++) rot[lane][e] = R[e];

        if (lane >= 1) {
            int base = (lane-1)*9;
            #pragma unroll
            for (int e = 0; e < 9; e++)
                g_AT[(base+e)*B + b] = tf32r(R[e] - ((e == 0 || e == 4 || e == 8) ? 1.f : 0.f));
        }

        float bt[NB];
        #pragma unroll
        for (int l = 0; l < NB; l++) bt[l] = betas[b*NB + l];
        #pragma unroll
        for (int k = 0; k < 3; k++) {
            float a = g_jt[lane*3 + k];
            #pragma unroll
            for (int l = 0; l < NB; l++) a += bt[l] * g_JS[lane*30 + k*10 + l];
            jnt[lane][k] = a;
        }
    }
    if (lane < NB)  g_AT[(P + lane)*B + b] = tf32r(betas[b*NB + lane]);
    if (lane >= 25) g_AT[(192 + lane)*B + b] = 0.f;   // rows 217..223
    __syncthreads();

    if (lane == 0) {
        #pragma unroll
        for (int m = 0; m < 3; m++) {
            G[0][m*4+0] = rot[0][m*3+0];
            G[0][m*4+1] = rot[0][m*3+1];
            G[0][m*4+2] = rot[0][m*3+2];
            G[0][m*4+3] = jnt[0][m];
        }
        for (int j = 1; j < J; j++) {
            int p = c_parents[j];
            float t0 = jnt[j][0] - jnt[p][0];
            float t1 = jnt[j][1] - jnt[p][1];
            float t2 = jnt[j][2] - jnt[p][2];
            #pragma unroll
            for (int m = 0; m < 3; m++) {
                float p0 = G[p][m*4+0], p1 = G[p][m*4+1], p2 = G[p][m*4+2], p3 = G[p][m*4+3];
                G[j][m*4+0] = p0*rot[j][0] + p1*rot[j][3] + p2*rot[j][6];
                G[j][m*4+1] = p0*rot[j][1] + p1*rot[j][4] + p2*rot[j][7];
                G[j][m*4+2] = p0*rot[j][2] + p1*rot[j][5] + p2*rot[j][8];
                G[j][m*4+3] = p0*t0 + p1*t1 + p2*t2 + p3;
            }
        }
    }
    __syncthreads();

    if (lane < J) {
        int j = lane;
        float tx = trans[b*3+0], ty = trans[b*3+1], tz = trans[b*3+2];
        float* oj = out_joints + ((size_t)b*J + j)*3;
        oj[0] = G[j][3]  + tx;
        oj[1] = G[j][7]  + ty;
        oj[2] = G[j][11] + tz;

        float* rl = g_rel + ((size_t)b*J + j)*12;
        #pragma unroll
        for (int m = 0; m < 3; m++) {
            float corr = G[j][m*4+0]*jnt[j][0] + G[j][m*4+1]*jnt[j][1] + G[j][m*4+2]*jnt[j][2];
            rl[m*4+0] = G[j][m*4+0];
            rl[m*4+1] = G[j][m*4+1];
            rl[m*4+2] = G[j][m*4+2];
            rl[m*4+3] = G[j][m*4+3] - corr;
        }
    }
}

// ---------------------------------------------------------------------------
// B-row loader for K3: raw fp32 bits (mma.tf32 hardware uses tf32 fields).
// ---------------------------------------------------------------------------
__device__ __forceinline__ void load_B_row(float* dst, int k, int cbase,
                                           const float* __restrict__ posedirs,
                                           const float* __restrict__ sd) {
    if (k < P) {
        if (cbase + 8 <= N3) {
            const float2* s = reinterpret_cast<const float2*>(posedirs + (size_t)k*N3 + cbase);
            #pragma unroll
            for (int i = 0; i < 4; i++) {
                float2 v = s[i];
                dst[2*i]   = v.x;
                dst[2*i+1] = v.y;
            }
        } else {
            #pragma unroll
            for (int i = 0; i < 8; i++) {
                int c = cbase + i;
                dst[i] = (c < N3) ? posedirs[(size_t)k*N3 + c] : 0.f;
            }
        }
    } else if (k < P + NB) {
        int l = k - P;
        #pragma unroll
        for (int i = 0; i < 8; i++) {
            int c = cbase + i;
            dst[i] = (c < N3) ? sd[(size_t)c*NB + l] : 0.f;
        }
    } else {
        #pragma unroll
        for (int i = 0; i < 8; i++) dst[i] = 0.f;
    }
}

// ---------------------------------------------------------------------------
// K3: TF32 GEMM, single-sync double buffer, B loaded direct (no pack).
// ---------------------------------------------------------------------------
#define BK3 16
#define SST 136
__global__ void __launch_bounds__(256) k3_tf32(const float* __restrict__ vt,
                                               const float* __restrict__ posedirs,
                                               const float* __restrict__ sd) {
    __shared__ float sA[2][BK3][SST];
    __shared__ float sB[2][BK3][SST];

    int tid  = threadIdx.x;
    int warp = tid >> 5, lane = tid & 31;
    int wm = warp >> 2;
    int wn = warp & 3;
    int gr = lane >> 2;
    int tg = lane & 3;

    int c0 = blockIdx.x * 128;
    int b0 = blockIdx.y * 128;

    int lk = tid >> 4;
    int lc = (tid & 15) * 8;

    float acc[4][4][4];
    #pragma unroll
    for (int mi = 0; mi < 4; mi++)
        #pragma unroll
        for (int ni = 0; ni < 4; ni++)
            #pragma unroll
            for (int r = 0; r < 4; r++) acc[mi][ni][r] = 0.f;

    {
        const float4* ga = reinterpret_cast<const float4*>(g_AT + (size_t)lk*B + b0 + lc);
        float bv[8];
        load_B_row(bv, lk, c0 + lc, posedirs, sd);
        float4 a0 = ga[0], a1 = ga[1];
        *reinterpret_cast<float4*>(&sA[0][lk][lc])     = a0;
        *reinterpret_cast<float4*>(&sA[0][lk][lc + 4]) = a1;
        *reinterpret_cast<float4*>(&sB[0][lk][lc])     = *reinterpret_cast<float4*>(bv);
        *reinterpret_cast<float4*>(&sB[0][lk][lc + 4]) = *reinterpret_cast<float4*>(bv + 4);
    }
    __syncthreads();

    const int NST = KT / BK3;    // 14
    for (int st = 0; st < NST; st++) {
        float4 pa0, pa1;
        float pbv[8];
        bool has_next = (st + 1 < NST);
        if (has_next) {
            int k = (st + 1) * BK3 + lk;
            const float4* ga = reinterpret_cast<const float4*>(g_AT + (size_t)k*B + b0 + lc);
            pa0 = ga[0]; pa1 = ga[1];
            load_B_row(pbv, k, c0 + lc, posedirs, sd);
        }
        int buf = st & 1;

        #pragma unroll
        for (int ks = 0; ks < 2; ks++) {
            int kb = ks * 8;
            uint32_t bfr[4][2];
            #pragma unroll
            for (int ni = 0; ni < 4; ni++) {
                int n = wn*32 + ni*8 + gr;
                bfr[ni][0] = __float_as_uint(sB[buf][kb + tg][n]);
                bfr[ni][1] = __float_as_uint(sB[buf][kb + tg + 4][n]);
            }
            uint32_t afr[4][4];
            #pragma unroll
            for (int mi = 0; mi < 4; mi++) {
                int m = wm*64 + mi*16 + gr;
                afr[mi][0] = __float_as_uint(sA[buf][kb + tg][m]);
                afr[mi][1] = __float_as_uint(sA[buf][kb + tg][m + 8]);
                afr[mi][2] = __float_as_uint(sA[buf][kb + tg + 4][m]);
                afr[mi][3] = __float_as_uint(sA[buf][kb + tg + 4][m + 8]);
            }
            #pragma unroll
            for (int mi = 0; mi < 4; mi++)
                #pragma unroll
                for (int ni = 0; ni < 4; ni++)
                    MMA_TF32(acc[mi][ni], afr[mi][0], afr[mi][1], afr[mi][2], afr[mi][3],
                             bfr[ni][0], bfr[ni][1]);
        }

        if (has_next) {
            int nb = 1 - buf;
            *reinterpret_cast<float4*>(&sA[nb][lk][lc])     = pa0;
            *reinterpret_cast<float4*>(&sA[nb][lk][lc + 4]) = pa1;
            *reinterpret_cast<float4*>(&sB[nb][lk][lc])     = *reinterpret_cast<float4*>(pbv);
            *reinterpret_cast<float4*>(&sB[nb][lk][lc + 4]) = *reinterpret_cast<float4*>(pbv + 4);
            __syncthreads();
        }
    }

    #pragma unroll
    for (int mi = 0; mi < 4; mi++) {
        #pragma unroll
        for (int half = 0; half < 2; half++) {
            int b = b0 + wm*64 + mi*16 + gr + half*8;
            #pragma unroll
            for (int ni = 0; ni < 4; ni++) {
                int c = c0 + wn*32 + ni*8 + tg*2;
                float v0 = (c     < N3) ? vt[c]     : 0.f;
                float v1 = (c + 1 < N3) ? vt[c + 1] : 0.f;
                float2 o = make_float2(acc[mi][ni][half*2]     + v0,
                                       acc[mi][ni][half*2 + 1] + v1);
                *reinterpret_cast<float2*>(g_vposed + (size_t)b*VS + c) = o;
            }
        }
    }
}

// ---------------------------------------------------------------------------
// K4: scalar skinning (R3 version — measured 61.3us, regs 80, fma 48%).
// out = trans + sum_j w[v,j] * (R_j*vp + t_j); 4 verts/lane; rel in smem.
// ---------------------------------------------------------------------------
__global__ void __launch_bounds__(256) k4_skin(const float* __restrict__ weights,
                                               const float* __restrict__ trans,
                                               float* __restrict__ out) {
    int tid = threadIdx.x;        // 256 = 8 warps
    int warp = tid >> 5;
    int lane = tid & 31;
    int b = blockIdx.y * 8 + warp;

    __shared__ float4 s_rel[8][J*3];
    {
        const float4* src = reinterpret_cast<const float4*>(g_rel);
        for (int i = tid; i < 8*J*3; i += 256) {
            int bl = i / (J*3), e = i % (J*3);
            s_rel[bl][e] = src[(size_t)(blockIdx.y*8 + bl)*(J*3) + e];
        }
    }
    __syncthreads();

    float t0 = trans[b*3+0], t1 = trans[b*3+1], t2 = trans[b*3+2];
    const float4* rel = s_rel[warp];
    const size_t bbase = (size_t)b * VS;

    int v0 = blockIdx.x * 128;
    int v[4]; bool ok[4];
    float vx[4], vy[4], vz[4], ox[4], oy[4], oz[4];
    #pragma unroll
    for (int u = 0; u < 4; u++) {
        int vv = v0 + u*32 + lane;
        ok[u] = vv < V;
        v[u] = ok[u] ? vv : (V - 1);
        vx[u] = g_vposed[bbase + v[u]*3 + 0];
        vy[u] = g_vposed[bbase + v[u]*3 + 1];
        vz[u] = g_vposed[bbase + v[u]*3 + 2];
        ox[u] = t0; oy[u] = t1; oz[u] = t2;
    }

    const float4* wv0 = reinterpret_cast<const float4*>(weights + (size_t)v[0]*J);
    const float4* wv1 = reinterpret_cast<const float4*>(weights + (size_t)v[1]*J);
    const float4* wv2 = reinterpret_cast<const float4*>(weights + (size_t)v[2]*J);
    const float4* wv3 = reinterpret_cast<const float4*>(weights + (size_t)v[3]*J);

    #pragma unroll
    for (int q = 0; q < 6; q++) {
        float4 w[4];
        w[0] = wv0[q]; w[1] = wv1[q]; w[2] = wv2[q]; w[3] = wv3[q];
        #pragma unroll
        for (int jj = 0; jj < 4; jj++) {
            int j = q*4 + jj;
            float4 r0 = rel[j*3 + 0];
            float4 r1 = rel[j*3 + 1];
            float4 r2 = rel[j*3 + 2];
            #pragma unroll
            for (int u = 0; u < 4; u++) {
                float wj = (jj == 0) ? w[u].x : (jj == 1) ? w[u].y : (jj == 2) ? w[u].z : w[u].w;
                float rx = fmaf(r0.x, vx[u], fmaf(r0.y, vy[u], fmaf(r0.z, vz[u], r0.w)));
                float ry = fmaf(r1.x, vx[u], fmaf(r1.y, vy[u], fmaf(r1.z, vz[u], r1.w)));
                float rz = fmaf(r2.x, vx[u], fmaf(r2.y, vy[u], fmaf(r2.z, vz[u], r2.w)));
                ox[u] = fmaf(wj, rx, ox[u]);
                oy[u] = fmaf(wj, ry, oy[u]);
                oz[u] = fmaf(wj, rz, oz[u]);
            }
        }
    }

    #pragma unroll
    for (int u = 0; u < 4; u++) {
        if (ok[u]) {
            float* o = out + ((size_t)b*V + v[u])*3;
            o[0] = ox[u]; o[1] = oy[u]; o[2] = oz[u];
        }
    }
}

// ---------------------------------------------------------------------------
extern "C" void kernel_launch(void* const* d_in, const int* in_sizes, int n_in,
                              void* d_out, int out_size) {
    const float* root_orient = (const float*)d_in[0];
    const float* pose_body   = (const float*)d_in[1];
    const float* pose_hand   = (const float*)d_in[2];
    const float* betas       = (const float*)d_in[3];
    const float* trans       = (const float*)d_in[4];
    const float* v_template  = (const float*)d_in[5];
    const float* shapedirs   = (const float*)d_in[6];
    const float* posedirs    = (const float*)d_in[7];
    const float* J_regressor = (const float*)d_in[8];
    const float* weights     = (const float*)d_in[9];

    float* out = (float*)d_out;
    float* out_joints = out + (size_t)B * V * 3;

    k1_regress<<<dim3(J, 33), 256>>>(J_regressor, v_template, shapedirs);
    k2_pose<<<B, 32>>>(root_orient, pose_body, pose_hand, betas, trans, out_joints);
    k3_tf32<<<dim3(VS/128, B/128), 256>>>(v_template, posedirs, shapedirs);
    k4_skin<<<dim3((V + 127)/128, B/8), 256>>>(weights, trans, out);
}